// round 1
// baseline (speedup 1.0000x reference)
#include <cuda_runtime.h>
#include <cstdint>

// Problem constants
#define B_      32
#define NHEAD   32
#define NKV     8
#define NREP    4
#define HDIM    128
#define HIDDEN_ 4096
#define QKV_OUT_ 6144          // (8*2+32)*128
#define QD      4096           // NHEAD*HDIM
#define KD      1024           // NKV*HDIM
#define PAST    2048
#define T_TOT   2049           // PAST + 1
#define SCALE_  0.08838834764831845f  // 1/sqrt(128)

// d_out layout: [out (32*32*128)] [k_cat (32*2049*8*128)] [v_cat (...)]
#define OFF_OUT 0
#define SZ_OUT  (B_*NHEAD*HDIM)                 // 131072
#define OFF_K   (SZ_OUT)
#define SZ_KC   ((size_t)B_*T_TOT*NKV*HDIM)     // 67141632
#define OFF_V   (OFF_K + SZ_KC)

// GEMM split-K
#define KSPLIT  8
#define KPER    (HIDDEN_/KSPLIT)                // 512
#define KC      32
#define NTILE   128

// attention chunking
#define TCHUNK  256
#define NCHUNK  9                                // ceil(2049/256)

// ---------------- scratch (no allocations allowed) ----------------
__device__ float g_part[KSPLIT * B_ * QKV_OUT_];          // 6.3 MB
__device__ float g_q[B_ * QD];                            // 0.5 MB
__device__ float g_pm[B_ * NKV * NCHUNK * NREP];
__device__ float g_pl[B_ * NKV * NCHUNK * NREP];
__device__ float g_pacc[B_ * NKV * NCHUNK * NREP * HDIM]; // 4.7 MB

// ---------------- Kernel 1: QKV GEMM (fp32, split-K partials) ----------------
// C[b,o] partial over K-slice. Block: 32 (M) x 128 (N) tile, 256 threads.
// Thread (ty,tx) computes m = {ty*2, ty*2+1}, n = {tx*4..tx*4+3, 64+tx*4..+3}
__global__ __launch_bounds__(256) void gemm_kernel(
    const float* __restrict__ X, const float* __restrict__ W)
{
    __shared__ float Xs[KC][34];
    __shared__ float Ws[KC][132];
    const int tid = threadIdx.x;
    const int tx = tid & 15, ty = tid >> 4;
    const int o0 = blockIdx.x * NTILE;
    const int k0 = blockIdx.y * KPER;

    float c[2][8];
#pragma unroll
    for (int i = 0; i < 2; i++)
#pragma unroll
        for (int j = 0; j < 8; j++) c[i][j] = 0.f;

    for (int kc = 0; kc < KPER; kc += KC) {
        // load X tile: 32 rows x 32 k = 256 float4, one per thread
        {
            int r = tid >> 3;             // batch row 0..31
            int c4 = tid & 7;             // float4 within 32 k
            float4 v = *(const float4*)&X[(size_t)r * HIDDEN_ + k0 + kc + c4 * 4];
            Xs[c4*4+0][r] = v.x; Xs[c4*4+1][r] = v.y;
            Xs[c4*4+2][r] = v.z; Xs[c4*4+3][r] = v.w;
        }
        // load W tile: 128 o x 32 k = 1024 float4, 4 per thread (transpose to Ws[k][o])
        {
            int o = tid >> 1;             // 0..127
            int half = tid & 1;           // 2 threads per o, 16 k each
            const float4* src = (const float4*)&W[(size_t)(o0 + o) * HIDDEN_ + k0 + kc + half * 16];
#pragma unroll
            for (int i = 0; i < 4; i++) {
                float4 v = src[i];
                int kk = half * 16 + i * 4;
                Ws[kk+0][o] = v.x; Ws[kk+1][o] = v.y;
                Ws[kk+2][o] = v.z; Ws[kk+3][o] = v.w;
            }
        }
        __syncthreads();
#pragma unroll
        for (int k = 0; k < KC; k++) {
            float2 a = *(const float2*)&Xs[k][ty * 2];
            float4 w0 = *(const float4*)&Ws[k][tx * 4];
            float4 w1 = *(const float4*)&Ws[k][64 + tx * 4];
            c[0][0] += a.x * w0.x; c[0][1] += a.x * w0.y;
            c[0][2] += a.x * w0.z; c[0][3] += a.x * w0.w;
            c[0][4] += a.x * w1.x; c[0][5] += a.x * w1.y;
            c[0][6] += a.x * w1.z; c[0][7] += a.x * w1.w;
            c[1][0] += a.y * w0.x; c[1][1] += a.y * w0.y;
            c[1][2] += a.y * w0.z; c[1][3] += a.y * w0.w;
            c[1][4] += a.y * w1.x; c[1][5] += a.y * w1.y;
            c[1][6] += a.y * w1.z; c[1][7] += a.y * w1.w;
        }
        __syncthreads();
    }
    // store partials
    const int ksb = blockIdx.y * B_;
#pragma unroll
    for (int mi = 0; mi < 2; mi++) {
        int b = ty * 2 + mi;
        float* dst = &g_part[(size_t)(ksb + b) * QKV_OUT_ + o0];
        *(float4*)&dst[tx * 4]      = make_float4(c[mi][0], c[mi][1], c[mi][2], c[mi][3]);
        *(float4*)&dst[64 + tx * 4] = make_float4(c[mi][4], c[mi][5], c[mi][6], c[mi][7]);
    }
}

// ---------------- Kernel 2: split-K reduce + bias + scatter ----------------
__global__ __launch_bounds__(256) void gemm_reduce_kernel(
    const float* __restrict__ bias, float* __restrict__ out)
{
    int i = blockIdx.x * 256 + threadIdx.x;
    if (i >= B_ * QKV_OUT_) return;
    int b = i / QKV_OUT_, o = i - b * QKV_OUT_;
    float s = bias[o];
#pragma unroll
    for (int ks = 0; ks < KSPLIT; ks++)
        s += g_part[(size_t)(ks * B_ + b) * QKV_OUT_ + o];
    if (o < QD) {
        g_q[b * QD + o] = s;
    } else if (o < QD + KD) {
        int r = o - QD;   // kv*128 + d, contiguous
        out[OFF_K + ((size_t)b * T_TOT + PAST) * KD + r] = s;
    } else {
        int r = o - QD - KD;
        out[OFF_V + ((size_t)b * T_TOT + PAST) * KD + r] = s;
    }
}

// ---------------- Kernel 3: fused cache-copy + split-KV flash attention ----------------
// grid (NCHUNK, NKV, B_), 256 threads (8 warps), warp handles 32 consecutive t.
__global__ __launch_bounds__(256) void attn_kernel(
    const float* __restrict__ Kc, const float* __restrict__ Vc,
    const float* __restrict__ mask, float* __restrict__ out)
{
    const int ch = blockIdx.x, kv = blockIdx.y, b = blockIdx.z;
    const int w = threadIdx.x >> 5, lane = threadIdx.x & 31;

    // q for the 4 GQA heads of this kv head (each lane owns 4 dims)
    float4 q[NREP];
#pragma unroll
    for (int h = 0; h < NREP; h++)
        q[h] = *(const float4*)&g_q[(size_t)b * QD + (kv * NREP + h) * HDIM + lane * 4];

    float m[NREP], l[NREP];
    float4 acc[NREP];
#pragma unroll
    for (int h = 0; h < NREP; h++) {
        m[h] = -1e30f; l[h] = 0.f;
        acc[h] = make_float4(0.f, 0.f, 0.f, 0.f);
    }

    const int t0 = ch * TCHUNK + w * 32;
    for (int j = 0; j < 32; j++) {
        int t = t0 + j;
        if (t >= T_TOT) break;
        size_t dsti = (((size_t)b * T_TOT + t) * NKV + kv) * HDIM;
        float4 k4, v4;
        if (t < PAST) {
            size_t srci = (((size_t)b * PAST + t) * NKV + kv) * HDIM;
            k4 = ((const float4*)(Kc + srci))[lane];
            v4 = ((const float4*)(Vc + srci))[lane];
            ((float4*)(out + OFF_K + dsti))[lane] = k4;   // fused copy
            ((float4*)(out + OFF_V + dsti))[lane] = v4;
        } else {
            k4 = ((const float4*)(out + OFF_K + dsti))[lane]; // new token (written by reduce)
            v4 = ((const float4*)(out + OFF_V + dsti))[lane];
        }
        float s[NREP];
#pragma unroll
        for (int h = 0; h < NREP; h++)
            s[h] = q[h].x * k4.x + q[h].y * k4.y + q[h].z * k4.z + q[h].w * k4.w;
#pragma unroll
        for (int off = 16; off; off >>= 1) {
#pragma unroll
            for (int h = 0; h < NREP; h++)
                s[h] += __shfl_xor_sync(0xFFFFFFFFu, s[h], off);
        }
        float mk = __ldg(&mask[(size_t)b * T_TOT + t]);
#pragma unroll
        for (int h = 0; h < NREP; h++) {
            float sv = s[h] * SCALE_ + mk;
            float mn = fmaxf(m[h], sv);
            float corr = __expf(m[h] - mn);
            float p = __expf(sv - mn);
            l[h] = l[h] * corr + p;
            acc[h].x = acc[h].x * corr + p * v4.x;
            acc[h].y = acc[h].y * corr + p * v4.y;
            acc[h].z = acc[h].z * corr + p * v4.z;
            acc[h].w = acc[h].w * corr + p * v4.w;
            m[h] = mn;
        }
    }

    // block combine across 8 warps
    __shared__ float sm_m[8][NREP];
    __shared__ float sm_l[8][NREP];
    __shared__ float sm_acc[8][NREP][HDIM];
    if (lane < NREP) { sm_m[w][lane] = m[lane]; sm_l[w][lane] = l[lane]; }
#pragma unroll
    for (int h = 0; h < NREP; h++)
        *(float4*)&sm_acc[w][h][lane * 4] = acc[h];
    __syncthreads();

    const int base = ((b * NKV + kv) * NCHUNK + ch) * NREP;
    for (int e = threadIdx.x; e < NREP * HDIM; e += 256) {
        int h = e >> 7, d = e & 127;
        float M = sm_m[0][h];
#pragma unroll
        for (int ww = 1; ww < 8; ww++) M = fmaxf(M, sm_m[ww][h]);
        float a = 0.f;
#pragma unroll
        for (int ww = 0; ww < 8; ww++)
            a += sm_acc[ww][h][d] * __expf(sm_m[ww][h] - M);
        g_pacc[(size_t)(base + h) * HDIM + d] = a;
    }
    if (threadIdx.x < NREP) {
        int h = threadIdx.x;
        float M = sm_m[0][h];
#pragma unroll
        for (int ww = 1; ww < 8; ww++) M = fmaxf(M, sm_m[ww][h]);
        float L = 0.f;
#pragma unroll
        for (int ww = 0; ww < 8; ww++)
            L += sm_l[ww][h] * __expf(sm_m[ww][h] - M);
        g_pm[base + h] = M;
        g_pl[base + h] = L;
    }
}

// ---------------- Kernel 4: cross-chunk softmax reduce ----------------
// grid (NHEAD, B_), 128 threads (one per d)
__global__ __launch_bounds__(128) void attn_final_kernel(float* __restrict__ out)
{
    const int h = blockIdx.x, b = blockIdx.y, d = threadIdx.x;
    const int kv = h >> 2, hh = h & 3;
    const int base0 = (b * NKV + kv) * NCHUNK;
    float M = -1e30f;
#pragma unroll
    for (int ch = 0; ch < NCHUNK; ch++)
        M = fmaxf(M, g_pm[(base0 + ch) * NREP + hh]);
    float L = 0.f, A = 0.f;
#pragma unroll
    for (int ch = 0; ch < NCHUNK; ch++) {
        int idx = (base0 + ch) * NREP + hh;
        float f = __expf(g_pm[idx] - M);
        L += g_pl[idx] * f;
        A += g_pacc[(size_t)idx * HDIM + d] * f;
    }
    out[OFF_OUT + ((size_t)b * NHEAD + h) * HDIM + d] = A / L;
}

// ---------------- launch ----------------
extern "C" void kernel_launch(void* const* d_in, const int* in_sizes, int n_in,
                              void* d_out, int out_size)
{
    const float* input_t = (const float*)d_in[0];
    const float* key_cache = (const float*)d_in[1];
    const float* value_cache = (const float*)d_in[2];
    // d_in[3] = max_position (unused), d_in[5] = beam_idx (unused)
    const float* attention_mask = (const float*)d_in[4];
    const float* W_qkv = (const float*)d_in[6];
    const float* b_qkv = (const float*)d_in[7];
    float* out = (float*)d_out;

    gemm_kernel<<<dim3(QKV_OUT_ / NTILE, KSPLIT), 256>>>(input_t, W_qkv);
    gemm_reduce_kernel<<<(B_ * QKV_OUT_ + 255) / 256, 256>>>(b_qkv, out);
    attn_kernel<<<dim3(NCHUNK, NKV, B_), 256>>>(key_cache, value_cache, attention_mask, out);
    attn_final_kernel<<<dim3(NHEAD, B_), 128>>>(out);
}

// round 2
// speedup vs baseline: 1.4218x; 1.4218x over previous
#include <cuda_runtime.h>
#include <cuda_bf16.h>
#include <cstdint>

// Problem constants
#define B_      32
#define NHEAD   32
#define NKV     8
#define NREP    4
#define HDIM    128
#define HIDDEN_ 4096
#define QKV_OUT_ 6144          // (8*2+32)*128
#define QD      4096           // NHEAD*HDIM
#define KD      1024           // NKV*HDIM
#define PAST    2048
#define T_TOT   2049           // PAST + 1
#define SCALE_  0.08838834764831845f  // 1/sqrt(128)

// d_out layout: [out (32*32*128)] [k_cat (32*2049*8*128)] [v_cat (...)]
#define OFF_OUT 0
#define SZ_OUT  (B_*NHEAD*HDIM)
#define OFF_K   (SZ_OUT)
#define SZ_KC   ((size_t)B_*T_TOT*NKV*HDIM)
#define OFF_V   (OFF_K + SZ_KC)

// GEMM split-K
#define KSPLIT  8
#define KPER    (HIDDEN_/KSPLIT)                // 512
#define KCH     32
#define NTILE   128
#define XSTR    40                               // smem row stride in bf16 (80B, 16B-aligned, conflict-free ldmatrix)

// attention chunking
#define TCHUNK  256
#define NCHUNK  9

// ---------------- scratch ----------------
__device__ float g_part[KSPLIT * B_ * QKV_OUT_];
__device__ float g_q[B_ * QD];
__device__ float g_pm[B_ * NKV * NCHUNK * NREP];
__device__ float g_pl[B_ * NKV * NCHUNK * NREP];
__device__ float g_pacc[B_ * NKV * NCHUNK * NREP * HDIM];

// ---------------- tensor-core helpers ----------------
__device__ __forceinline__ uint32_t smem_u32(const void* p) {
    return (uint32_t)__cvta_generic_to_shared(p);
}

__device__ __forceinline__ void ldsm4(uint32_t* r, uint32_t addr) {
    asm volatile("ldmatrix.sync.aligned.m8n8.x4.shared.b16 {%0,%1,%2,%3}, [%4];\n"
                 : "=r"(r[0]), "=r"(r[1]), "=r"(r[2]), "=r"(r[3]) : "r"(addr));
}

__device__ __forceinline__ void mma_bf16(float* d, const uint32_t* a, const uint32_t* b) {
    asm volatile(
        "mma.sync.aligned.m16n8k16.row.col.f32.bf16.bf16.f32 "
        "{%0,%1,%2,%3}, {%4,%5,%6,%7}, {%8,%9}, {%0,%1,%2,%3};\n"
        : "+f"(d[0]), "+f"(d[1]), "+f"(d[2]), "+f"(d[3])
        : "r"(a[0]), "r"(a[1]), "r"(a[2]), "r"(a[3]), "r"(b[0]), "r"(b[1]));
}

__device__ __forceinline__ void cvt_hilo(float x, __nv_bfloat16& h, __nv_bfloat16& l) {
    h = __float2bfloat16(x);
    l = __float2bfloat16(x - __bfloat162float(h));
}

// ---------------- Kernel 1: QKV GEMM via bf16 hi/lo split on tensor cores ----------------
// C[32, 6144] partial over K-slice. Block: 32(M) x 128(N), 256 threads (8 warps).
// Warp w: wm = w&1 (m16 tile), wn = w>>1 (n32 tile).
__global__ __launch_bounds__(256) void gemm_kernel(
    const float* __restrict__ X, const float* __restrict__ W)
{
    __shared__ __nv_bfloat16 Xh[32][XSTR], Xl[32][XSTR];
    __shared__ __nv_bfloat16 Wh[NTILE][XSTR], Wl[NTILE][XSTR];

    const int tid = threadIdx.x;
    const int warp = tid >> 5, lane = tid & 31;
    const int wm = warp & 1, wn = warp >> 1;
    const int o0 = blockIdx.x * NTILE;
    const int k0 = blockIdx.y * KPER;

    float d[4][4];
#pragma unroll
    for (int i = 0; i < 4; i++)
#pragma unroll
        for (int j = 0; j < 4; j++) d[i][j] = 0.f;

    // ldmatrix source addresses (constant across the k-loop except the kk offset)
    const int a_row = wm * 16 + (lane & 7) + ((lane & 8) ? 8 : 0);
    const int a_ks  = (lane & 16) ? 8 : 0;
    const int b_row0 = wn * 32 + (lane & 7) + ((lane & 16) ? 8 : 0);
    const int b_ks  = (lane & 8) ? 8 : 0;

    for (int kc = 0; kc < KPER; kc += KCH) {
        // --- load + convert X tile: 32 rows x 32 k (256 float4, 1/thread) ---
        {
            int r = tid >> 3, c4 = (tid & 7) * 4;
            float4 v = *(const float4*)&X[(size_t)r * HIDDEN_ + k0 + kc + c4];
            cvt_hilo(v.x, Xh[r][c4+0], Xl[r][c4+0]);
            cvt_hilo(v.y, Xh[r][c4+1], Xl[r][c4+1]);
            cvt_hilo(v.z, Xh[r][c4+2], Xl[r][c4+2]);
            cvt_hilo(v.w, Xh[r][c4+3], Xl[r][c4+3]);
        }
        // --- load + convert W tile: 128 o x 32 k (1024 float4, 4/thread) ---
        {
            int o = tid >> 1;
            int base = (tid & 1) * 16;
            const float4* src = (const float4*)&W[(size_t)(o0 + o) * HIDDEN_ + k0 + kc + base];
#pragma unroll
            for (int i = 0; i < 4; i++) {
                float4 v = src[i];
                int kk = base + i * 4;
                cvt_hilo(v.x, Wh[o][kk+0], Wl[o][kk+0]);
                cvt_hilo(v.y, Wh[o][kk+1], Wl[o][kk+1]);
                cvt_hilo(v.z, Wh[o][kk+2], Wl[o][kk+2]);
                cvt_hilo(v.w, Wh[o][kk+3], Wl[o][kk+3]);
            }
        }
        __syncthreads();

#pragma unroll
        for (int ks = 0; ks < 2; ks++) {
            const int kk = ks * 16;
            uint32_t ah[4], al[4];
            ldsm4(ah, smem_u32(&Xh[a_row][kk + a_ks]));
            ldsm4(al, smem_u32(&Xl[a_row][kk + a_ks]));
            // B fragments: two ldmatrix.x4 per plane cover n32
            uint32_t bh[8], bl[8];
            ldsm4(bh + 0, smem_u32(&Wh[b_row0][kk + b_ks]));
            ldsm4(bh + 4, smem_u32(&Wh[b_row0 + 16][kk + b_ks]));
            ldsm4(bl + 0, smem_u32(&Wl[b_row0][kk + b_ks]));
            ldsm4(bl + 4, smem_u32(&Wl[b_row0 + 16][kk + b_ks]));
#pragma unroll
            for (int nt = 0; nt < 4; nt++) {
                uint32_t* Bh = bh + nt * 2;
                uint32_t* Bl = bl + nt * 2;
                mma_bf16(d[nt], ah, Bh);   // hi*hi
                mma_bf16(d[nt], ah, Bl);   // hi*lo
                mma_bf16(d[nt], al, Bh);   // lo*hi
            }
        }
        __syncthreads();
    }

    // --- store partials: frag c0,c1 -> (row g, col 2t..), c2,c3 -> (row g+8) ---
    const int g = lane >> 2, t2 = (lane & 3) * 2;
    const int ksb = blockIdx.y * B_;
#pragma unroll
    for (int nt = 0; nt < 4; nt++) {
        int o = o0 + wn * 32 + nt * 8 + t2;
        int b0 = wm * 16 + g;
        float* dst0 = &g_part[(size_t)(ksb + b0) * QKV_OUT_ + o];
        dst0[0] = d[nt][0]; dst0[1] = d[nt][1];
        float* dst1 = &g_part[(size_t)(ksb + b0 + 8) * QKV_OUT_ + o];
        dst1[0] = d[nt][2]; dst1[1] = d[nt][3];
    }
}

// ---------------- Kernel 2: split-K reduce + bias + scatter ----------------
__global__ __launch_bounds__(256) void gemm_reduce_kernel(
    const float* __restrict__ bias, float* __restrict__ out)
{
    int i = blockIdx.x * 256 + threadIdx.x;
    if (i >= B_ * QKV_OUT_) return;
    int b = i / QKV_OUT_, o = i - b * QKV_OUT_;
    float s = bias[o];
#pragma unroll
    for (int ks = 0; ks < KSPLIT; ks++)
        s += g_part[(size_t)(ks * B_ + b) * QKV_OUT_ + o];
    if (o < QD) {
        g_q[b * QD + o] = s;
    } else if (o < QD + KD) {
        int r = o - QD;
        out[OFF_K + ((size_t)b * T_TOT + PAST) * KD + r] = s;
    } else {
        int r = o - QD - KD;
        out[OFF_V + ((size_t)b * T_TOT + PAST) * KD + r] = s;
    }
}

// ---------------- Kernel 3: fused cache-copy + split-KV flash attention ----------------
__global__ __launch_bounds__(256) void attn_kernel(
    const float* __restrict__ Kc, const float* __restrict__ Vc,
    const float* __restrict__ mask, float* __restrict__ out)
{
    const int ch = blockIdx.x, kv = blockIdx.y, b = blockIdx.z;
    const int w = threadIdx.x >> 5, lane = threadIdx.x & 31;

    float4 q[NREP];
#pragma unroll
    for (int h = 0; h < NREP; h++)
        q[h] = *(const float4*)&g_q[(size_t)b * QD + (kv * NREP + h) * HDIM + lane * 4];

    float m[NREP], l[NREP];
    float4 acc[NREP];
#pragma unroll
    for (int h = 0; h < NREP; h++) {
        m[h] = -1e30f; l[h] = 0.f;
        acc[h] = make_float4(0.f, 0.f, 0.f, 0.f);
    }

    const int t0 = ch * TCHUNK + w * 32;
    for (int j = 0; j < 32; j++) {
        int t = t0 + j;
        if (t >= T_TOT) break;
        size_t dsti = (((size_t)b * T_TOT + t) * NKV + kv) * HDIM;
        float4 k4, v4;
        if (t < PAST) {
            size_t srci = (((size_t)b * PAST + t) * NKV + kv) * HDIM;
            k4 = ((const float4*)(Kc + srci))[lane];
            v4 = ((const float4*)(Vc + srci))[lane];
            ((float4*)(out + OFF_K + dsti))[lane] = k4;
            ((float4*)(out + OFF_V + dsti))[lane] = v4;
        } else {
            k4 = ((const float4*)(out + OFF_K + dsti))[lane];
            v4 = ((const float4*)(out + OFF_V + dsti))[lane];
        }
        float s[NREP];
#pragma unroll
        for (int h = 0; h < NREP; h++)
            s[h] = q[h].x * k4.x + q[h].y * k4.y + q[h].z * k4.z + q[h].w * k4.w;
#pragma unroll
        for (int off = 16; off; off >>= 1) {
#pragma unroll
            for (int h = 0; h < NREP; h++)
                s[h] += __shfl_xor_sync(0xFFFFFFFFu, s[h], off);
        }
        float mk = __ldg(&mask[(size_t)b * T_TOT + t]);
#pragma unroll
        for (int h = 0; h < NREP; h++) {
            float sv = s[h] * SCALE_ + mk;
            float mn = fmaxf(m[h], sv);
            float corr = __expf(m[h] - mn);
            float p = __expf(sv - mn);
            l[h] = l[h] * corr + p;
            acc[h].x = acc[h].x * corr + p * v4.x;
            acc[h].y = acc[h].y * corr + p * v4.y;
            acc[h].z = acc[h].z * corr + p * v4.z;
            acc[h].w = acc[h].w * corr + p * v4.w;
            m[h] = mn;
        }
    }

    __shared__ float sm_m[8][NREP];
    __shared__ float sm_l[8][NREP];
    __shared__ float sm_acc[8][NREP][HDIM];
    if (lane < NREP) { sm_m[w][lane] = m[lane]; sm_l[w][lane] = l[lane]; }
#pragma unroll
    for (int h = 0; h < NREP; h++)
        *(float4*)&sm_acc[w][h][lane * 4] = acc[h];
    __syncthreads();

    const int base = ((b * NKV + kv) * NCHUNK + ch) * NREP;
    for (int e = threadIdx.x; e < NREP * HDIM; e += 256) {
        int h = e >> 7, dd = e & 127;
        float M = sm_m[0][h];
#pragma unroll
        for (int ww = 1; ww < 8; ww++) M = fmaxf(M, sm_m[ww][h]);
        float a = 0.f;
#pragma unroll
        for (int ww = 0; ww < 8; ww++)
            a += sm_acc[ww][h][dd] * __expf(sm_m[ww][h] - M);
        g_pacc[(size_t)(base + h) * HDIM + dd] = a;
    }
    if (threadIdx.x < NREP) {
        int h = threadIdx.x;
        float M = sm_m[0][h];
#pragma unroll
        for (int ww = 1; ww < 8; ww++) M = fmaxf(M, sm_m[ww][h]);
        float L = 0.f;
#pragma unroll
        for (int ww = 0; ww < 8; ww++)
            L += sm_l[ww][h] * __expf(sm_m[ww][h] - M);
        g_pm[base + h] = M;
        g_pl[base + h] = L;
    }
}

// ---------------- Kernel 4: cross-chunk softmax reduce ----------------
__global__ __launch_bounds__(128) void attn_final_kernel(float* __restrict__ out)
{
    const int h = blockIdx.x, b = blockIdx.y, d = threadIdx.x;
    const int kv = h >> 2, hh = h & 3;
    const int base0 = (b * NKV + kv) * NCHUNK;
    float M = -1e30f;
#pragma unroll
    for (int ch = 0; ch < NCHUNK; ch++)
        M = fmaxf(M, g_pm[(base0 + ch) * NREP + hh]);
    float L = 0.f, A = 0.f;
#pragma unroll
    for (int ch = 0; ch < NCHUNK; ch++) {
        int idx = (base0 + ch) * NREP + hh;
        float f = __expf(g_pm[idx] - M);
        L += g_pl[idx] * f;
        A += g_pacc[(size_t)idx * HDIM + d] * f;
    }
    out[OFF_OUT + ((size_t)b * NHEAD + h) * HDIM + d] = A / L;
}

// ---------------- launch ----------------
extern "C" void kernel_launch(void* const* d_in, const int* in_sizes, int n_in,
                              void* d_out, int out_size)
{
    const float* input_t = (const float*)d_in[0];
    const float* key_cache = (const float*)d_in[1];
    const float* value_cache = (const float*)d_in[2];
    const float* attention_mask = (const float*)d_in[4];
    const float* W_qkv = (const float*)d_in[6];
    const float* b_qkv = (const float*)d_in[7];
    float* out = (float*)d_out;

    gemm_kernel<<<dim3(QKV_OUT_ / NTILE, KSPLIT), 256>>>(input_t, W_qkv);
    gemm_reduce_kernel<<<(B_ * QKV_OUT_ + 255) / 256, 256>>>(b_qkv, out);
    attn_kernel<<<dim3(NCHUNK, NKV, B_), 256>>>(key_cache, value_cache, attention_mask, out);
    attn_final_kernel<<<dim3(NHEAD, B_), 128>>>(out);
}

// round 3
// speedup vs baseline: 1.4314x; 1.0067x over previous
#include <cuda_runtime.h>
#include <cuda_bf16.h>
#include <cstdint>

// Problem constants
#define B_      32
#define NHEAD   32
#define NKV     8
#define NREP    4
#define HDIM    128
#define HIDDEN_ 4096
#define QKV_OUT_ 6144          // (8*2+32)*128
#define QD      4096           // NHEAD*HDIM
#define KD      1024           // NKV*HDIM
#define PAST    2048
#define T_TOT   2049           // PAST + 1
#define SCALE_  0.08838834764831845f  // 1/sqrt(128)

// d_out layout: [out (32*32*128)] [k_cat (32*2049*8*128)] [v_cat (...)]
#define OFF_OUT 0
#define SZ_OUT  (B_*NHEAD*HDIM)
#define OFF_K   (SZ_OUT)
#define SZ_KC   ((size_t)B_*T_TOT*NKV*HDIM)
#define OFF_V   (OFF_K + SZ_KC)

// GEMM split-K
#define KSPLIT  8
#define KPER    (HIDDEN_/KSPLIT)                // 512
#define KCH     32
#define NTILE   128
#define XSTR    40                               // smem row stride in bf16 (80B, 16B-aligned, conflict-free ldmatrix)

// attention chunking
#define TCHUNK  256
#define NCHUNK  9

// ---------------- scratch ----------------
__device__ float g_part[KSPLIT * B_ * QKV_OUT_];
__device__ float g_q[B_ * QD];
__device__ float g_pm[B_ * NKV * NCHUNK * NREP];
__device__ float g_pl[B_ * NKV * NCHUNK * NREP];
__device__ float g_pacc[B_ * NKV * NCHUNK * NREP * HDIM];

// ---------------- tensor-core helpers ----------------
__device__ __forceinline__ uint32_t smem_u32(const void* p) {
    return (uint32_t)__cvta_generic_to_shared(p);
}

__device__ __forceinline__ void ldsm4(uint32_t* r, uint32_t addr) {
    asm volatile("ldmatrix.sync.aligned.m8n8.x4.shared.b16 {%0,%1,%2,%3}, [%4];\n"
                 : "=r"(r[0]), "=r"(r[1]), "=r"(r[2]), "=r"(r[3]) : "r"(addr));
}

__device__ __forceinline__ void mma_bf16(float* d, const uint32_t* a, const uint32_t* b) {
    asm volatile(
        "mma.sync.aligned.m16n8k16.row.col.f32.bf16.bf16.f32 "
        "{%0,%1,%2,%3}, {%4,%5,%6,%7}, {%8,%9}, {%0,%1,%2,%3};\n"
        : "+f"(d[0]), "+f"(d[1]), "+f"(d[2]), "+f"(d[3])
        : "r"(a[0]), "r"(a[1]), "r"(a[2]), "r"(a[3]), "r"(b[0]), "r"(b[1]));
}

__device__ __forceinline__ void cvt_hilo(float x, __nv_bfloat16& h, __nv_bfloat16& l) {
    h = __float2bfloat16(x);
    l = __float2bfloat16(x - __bfloat162float(h));
}

// ---------------- Kernel 1: QKV GEMM via bf16 hi/lo split on tensor cores ----------------
// C[32, 6144] partial over K-slice. Block: 32(M) x 128(N), 256 threads (8 warps).
// Warp w: wm = w&1 (m16 tile), wn = w>>1 (n32 tile).
__global__ __launch_bounds__(256) void gemm_kernel(
    const float* __restrict__ X, const float* __restrict__ W)
{
    __shared__ __nv_bfloat16 Xh[32][XSTR], Xl[32][XSTR];
    __shared__ __nv_bfloat16 Wh[NTILE][XSTR], Wl[NTILE][XSTR];

    const int tid = threadIdx.x;
    const int warp = tid >> 5, lane = tid & 31;
    const int wm = warp & 1, wn = warp >> 1;
    const int o0 = blockIdx.x * NTILE;
    const int k0 = blockIdx.y * KPER;

    float d[4][4];
#pragma unroll
    for (int i = 0; i < 4; i++)
#pragma unroll
        for (int j = 0; j < 4; j++) d[i][j] = 0.f;

    // ldmatrix source addresses (constant across the k-loop except the kk offset)
    const int a_row = wm * 16 + (lane & 7) + ((lane & 8) ? 8 : 0);
    const int a_ks  = (lane & 16) ? 8 : 0;
    const int b_row0 = wn * 32 + (lane & 7) + ((lane & 16) ? 8 : 0);
    const int b_ks  = (lane & 8) ? 8 : 0;

    for (int kc = 0; kc < KPER; kc += KCH) {
        // --- load + convert X tile: 32 rows x 32 k (256 float4, 1/thread) ---
        {
            int r = tid >> 3, c4 = (tid & 7) * 4;
            float4 v = *(const float4*)&X[(size_t)r * HIDDEN_ + k0 + kc + c4];
            cvt_hilo(v.x, Xh[r][c4+0], Xl[r][c4+0]);
            cvt_hilo(v.y, Xh[r][c4+1], Xl[r][c4+1]);
            cvt_hilo(v.z, Xh[r][c4+2], Xl[r][c4+2]);
            cvt_hilo(v.w, Xh[r][c4+3], Xl[r][c4+3]);
        }
        // --- load + convert W tile: 128 o x 32 k (1024 float4, 4/thread) ---
        {
            int o = tid >> 1;
            int base = (tid & 1) * 16;
            const float4* src = (const float4*)&W[(size_t)(o0 + o) * HIDDEN_ + k0 + kc + base];
#pragma unroll
            for (int i = 0; i < 4; i++) {
                float4 v = src[i];
                int kk = base + i * 4;
                cvt_hilo(v.x, Wh[o][kk+0], Wl[o][kk+0]);
                cvt_hilo(v.y, Wh[o][kk+1], Wl[o][kk+1]);
                cvt_hilo(v.z, Wh[o][kk+2], Wl[o][kk+2]);
                cvt_hilo(v.w, Wh[o][kk+3], Wl[o][kk+3]);
            }
        }
        __syncthreads();

#pragma unroll
        for (int ks = 0; ks < 2; ks++) {
            const int kk = ks * 16;
            uint32_t ah[4], al[4];
            ldsm4(ah, smem_u32(&Xh[a_row][kk + a_ks]));
            ldsm4(al, smem_u32(&Xl[a_row][kk + a_ks]));
            // B fragments: two ldmatrix.x4 per plane cover n32
            uint32_t bh[8], bl[8];
            ldsm4(bh + 0, smem_u32(&Wh[b_row0][kk + b_ks]));
            ldsm4(bh + 4, smem_u32(&Wh[b_row0 + 16][kk + b_ks]));
            ldsm4(bl + 0, smem_u32(&Wl[b_row0][kk + b_ks]));
            ldsm4(bl + 4, smem_u32(&Wl[b_row0 + 16][kk + b_ks]));
#pragma unroll
            for (int nt = 0; nt < 4; nt++) {
                uint32_t* Bh = bh + nt * 2;
                uint32_t* Bl = bl + nt * 2;
                mma_bf16(d[nt], ah, Bh);   // hi*hi
                mma_bf16(d[nt], ah, Bl);   // hi*lo
                mma_bf16(d[nt], al, Bh);   // lo*hi
            }
        }
        __syncthreads();
    }

    // --- store partials: frag c0,c1 -> (row g, col 2t..), c2,c3 -> (row g+8) ---
    const int g = lane >> 2, t2 = (lane & 3) * 2;
    const int ksb = blockIdx.y * B_;
#pragma unroll
    for (int nt = 0; nt < 4; nt++) {
        int o = o0 + wn * 32 + nt * 8 + t2;
        int b0 = wm * 16 + g;
        float* dst0 = &g_part[(size_t)(ksb + b0) * QKV_OUT_ + o];
        dst0[0] = d[nt][0]; dst0[1] = d[nt][1];
        float* dst1 = &g_part[(size_t)(ksb + b0 + 8) * QKV_OUT_ + o];
        dst1[0] = d[nt][2]; dst1[1] = d[nt][3];
    }
}

// ---------------- Kernel 2: split-K reduce + bias + scatter ----------------
__global__ __launch_bounds__(256) void gemm_reduce_kernel(
    const float* __restrict__ bias, float* __restrict__ out)
{
    int i = blockIdx.x * 256 + threadIdx.x;
    if (i >= B_ * QKV_OUT_) return;
    int b = i / QKV_OUT_, o = i - b * QKV_OUT_;
    float s = bias[o];
#pragma unroll
    for (int ks = 0; ks < KSPLIT; ks++)
        s += g_part[(size_t)(ks * B_ + b) * QKV_OUT_ + o];
    if (o < QD) {
        g_q[b * QD + o] = s;
    } else if (o < QD + KD) {
        int r = o - QD;
        out[OFF_K + ((size_t)b * T_TOT + PAST) * KD + r] = s;
    } else {
        int r = o - QD - KD;
        out[OFF_V + ((size_t)b * T_TOT + PAST) * KD + r] = s;
    }
}

// ---------------- Kernel 3: fused cache-copy + split-KV flash attention ----------------
__global__ __launch_bounds__(256) void attn_kernel(
    const float* __restrict__ Kc, const float* __restrict__ Vc,
    const float* __restrict__ mask, float* __restrict__ out)
{
    const int ch = blockIdx.x, kv = blockIdx.y, b = blockIdx.z;
    const int w = threadIdx.x >> 5, lane = threadIdx.x & 31;

    float4 q[NREP];
#pragma unroll
    for (int h = 0; h < NREP; h++)
        q[h] = *(const float4*)&g_q[(size_t)b * QD + (kv * NREP + h) * HDIM + lane * 4];

    float m[NREP], l[NREP];
    float4 acc[NREP];
#pragma unroll
    for (int h = 0; h < NREP; h++) {
        m[h] = -1e30f; l[h] = 0.f;
        acc[h] = make_float4(0.f, 0.f, 0.f, 0.f);
    }

    const int t0 = ch * TCHUNK + w * 32;
    for (int j = 0; j < 32; j++) {
        int t = t0 + j;
        if (t >= T_TOT) break;
        size_t dsti = (((size_t)b * T_TOT + t) * NKV + kv) * HDIM;
        float4 k4, v4;
        if (t < PAST) {
            size_t srci = (((size_t)b * PAST + t) * NKV + kv) * HDIM;
            k4 = ((const float4*)(Kc + srci))[lane];
            v4 = ((const float4*)(Vc + srci))[lane];
            ((float4*)(out + OFF_K + dsti))[lane] = k4;
            ((float4*)(out + OFF_V + dsti))[lane] = v4;
        } else {
            k4 = ((const float4*)(out + OFF_K + dsti))[lane];
            v4 = ((const float4*)(out + OFF_V + dsti))[lane];
        }
        float s[NREP];
#pragma unroll
        for (int h = 0; h < NREP; h++)
            s[h] = q[h].x * k4.x + q[h].y * k4.y + q[h].z * k4.z + q[h].w * k4.w;
#pragma unroll
        for (int off = 16; off; off >>= 1) {
#pragma unroll
            for (int h = 0; h < NREP; h++)
                s[h] += __shfl_xor_sync(0xFFFFFFFFu, s[h], off);
        }
        float mk = __ldg(&mask[(size_t)b * T_TOT + t]);
#pragma unroll
        for (int h = 0; h < NREP; h++) {
            float sv = s[h] * SCALE_ + mk;
            float mn = fmaxf(m[h], sv);
            float corr = __expf(m[h] - mn);
            float p = __expf(sv - mn);
            l[h] = l[h] * corr + p;
            acc[h].x = acc[h].x * corr + p * v4.x;
            acc[h].y = acc[h].y * corr + p * v4.y;
            acc[h].z = acc[h].z * corr + p * v4.z;
            acc[h].w = acc[h].w * corr + p * v4.w;
            m[h] = mn;
        }
    }

    __shared__ float sm_m[8][NREP];
    __shared__ float sm_l[8][NREP];
    __shared__ float sm_acc[8][NREP][HDIM];
    if (lane < NREP) { sm_m[w][lane] = m[lane]; sm_l[w][lane] = l[lane]; }
#pragma unroll
    for (int h = 0; h < NREP; h++)
        *(float4*)&sm_acc[w][h][lane * 4] = acc[h];
    __syncthreads();

    const int base = ((b * NKV + kv) * NCHUNK + ch) * NREP;
    for (int e = threadIdx.x; e < NREP * HDIM; e += 256) {
        int h = e >> 7, dd = e & 127;
        float M = sm_m[0][h];
#pragma unroll
        for (int ww = 1; ww < 8; ww++) M = fmaxf(M, sm_m[ww][h]);
        float a = 0.f;
#pragma unroll
        for (int ww = 0; ww < 8; ww++)
            a += sm_acc[ww][h][dd] * __expf(sm_m[ww][h] - M);
        g_pacc[(size_t)(base + h) * HDIM + dd] = a;
    }
    if (threadIdx.x < NREP) {
        int h = threadIdx.x;
        float M = sm_m[0][h];
#pragma unroll
        for (int ww = 1; ww < 8; ww++) M = fmaxf(M, sm_m[ww][h]);
        float L = 0.f;
#pragma unroll
        for (int ww = 0; ww < 8; ww++)
            L += sm_l[ww][h] * __expf(sm_m[ww][h] - M);
        g_pm[base + h] = M;
        g_pl[base + h] = L;
    }
}

// ---------------- Kernel 4: cross-chunk softmax reduce ----------------
__global__ __launch_bounds__(128) void attn_final_kernel(float* __restrict__ out)
{
    const int h = blockIdx.x, b = blockIdx.y, d = threadIdx.x;
    const int kv = h >> 2, hh = h & 3;
    const int base0 = (b * NKV + kv) * NCHUNK;
    float M = -1e30f;
#pragma unroll
    for (int ch = 0; ch < NCHUNK; ch++)
        M = fmaxf(M, g_pm[(base0 + ch) * NREP + hh]);
    float L = 0.f, A = 0.f;
#pragma unroll
    for (int ch = 0; ch < NCHUNK; ch++) {
        int idx = (base0 + ch) * NREP + hh;
        float f = __expf(g_pm[idx] - M);
        L += g_pl[idx] * f;
        A += g_pacc[(size_t)idx * HDIM + d] * f;
    }
    out[OFF_OUT + ((size_t)b * NHEAD + h) * HDIM + d] = A / L;
}

// ---------------- launch ----------------
extern "C" void kernel_launch(void* const* d_in, const int* in_sizes, int n_in,
                              void* d_out, int out_size)
{
    const float* input_t = (const float*)d_in[0];
    const float* key_cache = (const float*)d_in[1];
    const float* value_cache = (const float*)d_in[2];
    const float* attention_mask = (const float*)d_in[4];
    const float* W_qkv = (const float*)d_in[6];
    const float* b_qkv = (const float*)d_in[7];
    float* out = (float*)d_out;

    gemm_kernel<<<dim3(QKV_OUT_ / NTILE, KSPLIT), 256>>>(input_t, W_qkv);
    gemm_reduce_kernel<<<(B_ * QKV_OUT_ + 255) / 256, 256>>>(b_qkv, out);
    attn_kernel<<<dim3(NCHUNK, NKV, B_), 256>>>(key_cache, value_cache, attention_mask, out);
    attn_final_kernel<<<dim3(NHEAD, B_), 128>>>(out);
}

// round 4
// speedup vs baseline: 1.4359x; 1.0032x over previous
#include <cuda_runtime.h>
#include <cuda_bf16.h>
#include <cstdint>

// Problem constants
#define B_      32
#define NHEAD   32
#define NKV     8
#define NREP    4
#define HDIM    128
#define HIDDEN_ 4096
#define QKV_OUT_ 6144          // (8*2+32)*128
#define QD      4096           // NHEAD*HDIM
#define KD      1024           // NKV*HDIM
#define PAST    2048
#define T_TOT   2049           // PAST + 1
#define SCALE_  0.08838834764831845f  // 1/sqrt(128)

// d_out layout: [out (32*32*128)] [k_cat (32*2049*8*128)] [v_cat (...)]
#define OFF_OUT 0
#define SZ_OUT  (B_*NHEAD*HDIM)
#define OFF_K   (SZ_OUT)
#define SZ_KC   ((size_t)B_*T_TOT*NKV*HDIM)
#define OFF_V   (OFF_K + SZ_KC)

// GEMM split-K
#define KSPLIT  8
#define KPER    (HIDDEN_/KSPLIT)                // 512
#define KCH     32
#define NTILE   128
#define XSTR    40                               // smem row stride in bf16 (80B, 16B-aligned, conflict-free ldmatrix)

// attention chunking
#define TCHUNK  256
#define NCHUNK  9

// ---------------- scratch ----------------
__device__ float g_part[KSPLIT * B_ * QKV_OUT_];
__device__ float g_q[B_ * QD];
__device__ float g_pm[B_ * NKV * NCHUNK * NREP];
__device__ float g_pl[B_ * NKV * NCHUNK * NREP];
__device__ float g_pacc[B_ * NKV * NCHUNK * NREP * HDIM];

// ---------------- tensor-core helpers ----------------
__device__ __forceinline__ uint32_t smem_u32(const void* p) {
    return (uint32_t)__cvta_generic_to_shared(p);
}

__device__ __forceinline__ void ldsm4(uint32_t* r, uint32_t addr) {
    asm volatile("ldmatrix.sync.aligned.m8n8.x4.shared.b16 {%0,%1,%2,%3}, [%4];\n"
                 : "=r"(r[0]), "=r"(r[1]), "=r"(r[2]), "=r"(r[3]) : "r"(addr));
}

__device__ __forceinline__ void mma_bf16(float* d, const uint32_t* a, const uint32_t* b) {
    asm volatile(
        "mma.sync.aligned.m16n8k16.row.col.f32.bf16.bf16.f32 "
        "{%0,%1,%2,%3}, {%4,%5,%6,%7}, {%8,%9}, {%0,%1,%2,%3};\n"
        : "+f"(d[0]), "+f"(d[1]), "+f"(d[2]), "+f"(d[3])
        : "r"(a[0]), "r"(a[1]), "r"(a[2]), "r"(a[3]), "r"(b[0]), "r"(b[1]));
}

__device__ __forceinline__ void cvt_hilo(float x, __nv_bfloat16& h, __nv_bfloat16& l) {
    h = __float2bfloat16(x);
    l = __float2bfloat16(x - __bfloat162float(h));
}

// ---------------- Kernel 1: QKV GEMM via bf16 hi/lo split on tensor cores ----------------
// C[32, 6144] partial over K-slice. Block: 32(M) x 128(N), 256 threads (8 warps).
// Warp w: wm = w&1 (m16 tile), wn = w>>1 (n32 tile).
__global__ __launch_bounds__(256) void gemm_kernel(
    const float* __restrict__ X, const float* __restrict__ W)
{
    __shared__ __nv_bfloat16 Xh[32][XSTR], Xl[32][XSTR];
    __shared__ __nv_bfloat16 Wh[NTILE][XSTR], Wl[NTILE][XSTR];

    const int tid = threadIdx.x;
    const int warp = tid >> 5, lane = tid & 31;
    const int wm = warp & 1, wn = warp >> 1;
    const int o0 = blockIdx.x * NTILE;
    const int k0 = blockIdx.y * KPER;

    float d[4][4];
#pragma unroll
    for (int i = 0; i < 4; i++)
#pragma unroll
        for (int j = 0; j < 4; j++) d[i][j] = 0.f;

    // ldmatrix source addresses (constant across the k-loop except the kk offset)
    const int a_row = wm * 16 + (lane & 7) + ((lane & 8) ? 8 : 0);
    const int a_ks  = (lane & 16) ? 8 : 0;
    const int b_row0 = wn * 32 + (lane & 7) + ((lane & 16) ? 8 : 0);
    const int b_ks  = (lane & 8) ? 8 : 0;

    for (int kc = 0; kc < KPER; kc += KCH) {
        // --- load + convert X tile: 32 rows x 32 k (256 float4, 1/thread) ---
        {
            int r = tid >> 3, c4 = (tid & 7) * 4;
            float4 v = *(const float4*)&X[(size_t)r * HIDDEN_ + k0 + kc + c4];
            cvt_hilo(v.x, Xh[r][c4+0], Xl[r][c4+0]);
            cvt_hilo(v.y, Xh[r][c4+1], Xl[r][c4+1]);
            cvt_hilo(v.z, Xh[r][c4+2], Xl[r][c4+2]);
            cvt_hilo(v.w, Xh[r][c4+3], Xl[r][c4+3]);
        }
        // --- load + convert W tile: 128 o x 32 k (1024 float4, 4/thread) ---
        {
            int o = tid >> 1;
            int base = (tid & 1) * 16;
            const float4* src = (const float4*)&W[(size_t)(o0 + o) * HIDDEN_ + k0 + kc + base];
#pragma unroll
            for (int i = 0; i < 4; i++) {
                float4 v = src[i];
                int kk = base + i * 4;
                cvt_hilo(v.x, Wh[o][kk+0], Wl[o][kk+0]);
                cvt_hilo(v.y, Wh[o][kk+1], Wl[o][kk+1]);
                cvt_hilo(v.z, Wh[o][kk+2], Wl[o][kk+2]);
                cvt_hilo(v.w, Wh[o][kk+3], Wl[o][kk+3]);
            }
        }
        __syncthreads();

#pragma unroll
        for (int ks = 0; ks < 2; ks++) {
            const int kk = ks * 16;
            uint32_t ah[4], al[4];
            ldsm4(ah, smem_u32(&Xh[a_row][kk + a_ks]));
            ldsm4(al, smem_u32(&Xl[a_row][kk + a_ks]));
            // B fragments: two ldmatrix.x4 per plane cover n32
            uint32_t bh[8], bl[8];
            ldsm4(bh + 0, smem_u32(&Wh[b_row0][kk + b_ks]));
            ldsm4(bh + 4, smem_u32(&Wh[b_row0 + 16][kk + b_ks]));
            ldsm4(bl + 0, smem_u32(&Wl[b_row0][kk + b_ks]));
            ldsm4(bl + 4, smem_u32(&Wl[b_row0 + 16][kk + b_ks]));
#pragma unroll
            for (int nt = 0; nt < 4; nt++) {
                uint32_t* Bh = bh + nt * 2;
                uint32_t* Bl = bl + nt * 2;
                mma_bf16(d[nt], ah, Bh);   // hi*hi
                mma_bf16(d[nt], ah, Bl);   // hi*lo
                mma_bf16(d[nt], al, Bh);   // lo*hi
            }
        }
        __syncthreads();
    }

    // --- store partials: frag c0,c1 -> (row g, col 2t..), c2,c3 -> (row g+8) ---
    const int g = lane >> 2, t2 = (lane & 3) * 2;
    const int ksb = blockIdx.y * B_;
#pragma unroll
    for (int nt = 0; nt < 4; nt++) {
        int o = o0 + wn * 32 + nt * 8 + t2;
        int b0 = wm * 16 + g;
        float* dst0 = &g_part[(size_t)(ksb + b0) * QKV_OUT_ + o];
        dst0[0] = d[nt][0]; dst0[1] = d[nt][1];
        float* dst1 = &g_part[(size_t)(ksb + b0 + 8) * QKV_OUT_ + o];
        dst1[0] = d[nt][2]; dst1[1] = d[nt][3];
    }
}

// ---------------- Kernel 2: split-K reduce + bias + scatter ----------------
__global__ __launch_bounds__(256) void gemm_reduce_kernel(
    const float* __restrict__ bias, float* __restrict__ out)
{
    int i = blockIdx.x * 256 + threadIdx.x;
    if (i >= B_ * QKV_OUT_) return;
    int b = i / QKV_OUT_, o = i - b * QKV_OUT_;
    float s = bias[o];
#pragma unroll
    for (int ks = 0; ks < KSPLIT; ks++)
        s += g_part[(size_t)(ks * B_ + b) * QKV_OUT_ + o];
    if (o < QD) {
        g_q[b * QD + o] = s;
    } else if (o < QD + KD) {
        int r = o - QD;
        out[OFF_K + ((size_t)b * T_TOT + PAST) * KD + r] = s;
    } else {
        int r = o - QD - KD;
        out[OFF_V + ((size_t)b * T_TOT + PAST) * KD + r] = s;
    }
}

// ---------------- Kernel 3: fused cache-copy + split-KV flash attention ----------------
__global__ __launch_bounds__(256) void attn_kernel(
    const float* __restrict__ Kc, const float* __restrict__ Vc,
    const float* __restrict__ mask, float* __restrict__ out)
{
    const int ch = blockIdx.x, kv = blockIdx.y, b = blockIdx.z;
    const int w = threadIdx.x >> 5, lane = threadIdx.x & 31;

    float4 q[NREP];
#pragma unroll
    for (int h = 0; h < NREP; h++)
        q[h] = *(const float4*)&g_q[(size_t)b * QD + (kv * NREP + h) * HDIM + lane * 4];

    float m[NREP], l[NREP];
    float4 acc[NREP];
#pragma unroll
    for (int h = 0; h < NREP; h++) {
        m[h] = -1e30f; l[h] = 0.f;
        acc[h] = make_float4(0.f, 0.f, 0.f, 0.f);
    }

    const int t0 = ch * TCHUNK + w * 32;
    for (int j = 0; j < 32; j++) {
        int t = t0 + j;
        if (t >= T_TOT) break;
        size_t dsti = (((size_t)b * T_TOT + t) * NKV + kv) * HDIM;
        float4 k4, v4;
        if (t < PAST) {
            size_t srci = (((size_t)b * PAST + t) * NKV + kv) * HDIM;
            k4 = ((const float4*)(Kc + srci))[lane];
            v4 = ((const float4*)(Vc + srci))[lane];
            ((float4*)(out + OFF_K + dsti))[lane] = k4;
            ((float4*)(out + OFF_V + dsti))[lane] = v4;
        } else {
            k4 = ((const float4*)(out + OFF_K + dsti))[lane];
            v4 = ((const float4*)(out + OFF_V + dsti))[lane];
        }
        float s[NREP];
#pragma unroll
        for (int h = 0; h < NREP; h++)
            s[h] = q[h].x * k4.x + q[h].y * k4.y + q[h].z * k4.z + q[h].w * k4.w;
#pragma unroll
        for (int off = 16; off; off >>= 1) {
#pragma unroll
            for (int h = 0; h < NREP; h++)
                s[h] += __shfl_xor_sync(0xFFFFFFFFu, s[h], off);
        }
        float mk = __ldg(&mask[(size_t)b * T_TOT + t]);
#pragma unroll
        for (int h = 0; h < NREP; h++) {
            float sv = s[h] * SCALE_ + mk;
            float mn = fmaxf(m[h], sv);
            float corr = __expf(m[h] - mn);
            float p = __expf(sv - mn);
            l[h] = l[h] * corr + p;
            acc[h].x = acc[h].x * corr + p * v4.x;
            acc[h].y = acc[h].y * corr + p * v4.y;
            acc[h].z = acc[h].z * corr + p * v4.z;
            acc[h].w = acc[h].w * corr + p * v4.w;
            m[h] = mn;
        }
    }

    __shared__ float sm_m[8][NREP];
    __shared__ float sm_l[8][NREP];
    __shared__ float sm_acc[8][NREP][HDIM];
    if (lane < NREP) { sm_m[w][lane] = m[lane]; sm_l[w][lane] = l[lane]; }
#pragma unroll
    for (int h = 0; h < NREP; h++)
        *(float4*)&sm_acc[w][h][lane * 4] = acc[h];
    __syncthreads();

    const int base = ((b * NKV + kv) * NCHUNK + ch) * NREP;
    for (int e = threadIdx.x; e < NREP * HDIM; e += 256) {
        int h = e >> 7, dd = e & 127;
        float M = sm_m[0][h];
#pragma unroll
        for (int ww = 1; ww < 8; ww++) M = fmaxf(M, sm_m[ww][h]);
        float a = 0.f;
#pragma unroll
        for (int ww = 0; ww < 8; ww++)
            a += sm_acc[ww][h][dd] * __expf(sm_m[ww][h] - M);
        g_pacc[(size_t)(base + h) * HDIM + dd] = a;
    }
    if (threadIdx.x < NREP) {
        int h = threadIdx.x;
        float M = sm_m[0][h];
#pragma unroll
        for (int ww = 1; ww < 8; ww++) M = fmaxf(M, sm_m[ww][h]);
        float L = 0.f;
#pragma unroll
        for (int ww = 0; ww < 8; ww++)
            L += sm_l[ww][h] * __expf(sm_m[ww][h] - M);
        g_pm[base + h] = M;
        g_pl[base + h] = L;
    }
}

// ---------------- Kernel 4: cross-chunk softmax reduce ----------------
__global__ __launch_bounds__(128) void attn_final_kernel(float* __restrict__ out)
{
    const int h = blockIdx.x, b = blockIdx.y, d = threadIdx.x;
    const int kv = h >> 2, hh = h & 3;
    const int base0 = (b * NKV + kv) * NCHUNK;
    float M = -1e30f;
#pragma unroll
    for (int ch = 0; ch < NCHUNK; ch++)
        M = fmaxf(M, g_pm[(base0 + ch) * NREP + hh]);
    float L = 0.f, A = 0.f;
#pragma unroll
    for (int ch = 0; ch < NCHUNK; ch++) {
        int idx = (base0 + ch) * NREP + hh;
        float f = __expf(g_pm[idx] - M);
        L += g_pl[idx] * f;
        A += g_pacc[(size_t)idx * HDIM + d] * f;
    }
    out[OFF_OUT + ((size_t)b * NHEAD + h) * HDIM + d] = A / L;
}

// ---------------- launch ----------------
extern "C" void kernel_launch(void* const* d_in, const int* in_sizes, int n_in,
                              void* d_out, int out_size)
{
    const float* input_t = (const float*)d_in[0];
    const float* key_cache = (const float*)d_in[1];
    const float* value_cache = (const float*)d_in[2];
    const float* attention_mask = (const float*)d_in[4];
    const float* W_qkv = (const float*)d_in[6];
    const float* b_qkv = (const float*)d_in[7];
    float* out = (float*)d_out;

    gemm_kernel<<<dim3(QKV_OUT_ / NTILE, KSPLIT), 256>>>(input_t, W_qkv);
    gemm_reduce_kernel<<<(B_ * QKV_OUT_ + 255) / 256, 256>>>(b_qkv, out);
    attn_kernel<<<dim3(NCHUNK, NKV, B_), 256>>>(key_cache, value_cache, attention_mask, out);
    attn_final_kernel<<<dim3(NHEAD, B_), 128>>>(out);
}